// round 8
// baseline (speedup 1.0000x reference)
#include <cuda_runtime.h>
#include <climits>

// Fixed problem shape: B=8, C=1, H=W=768.
#define BB    8
#define HH    768
#define WW    768
#define HWSZ  (HH * WW)          // 589824
#define NTOT  (BB * HWSZ)        // 4718592
#define N4    (NTOT / 4)

#define TS        32
#define TILES_X   24
#define TILES_Y   24
#define TPI       (TILES_X * TILES_Y)    // 576
#define NTILES    (BB * TPI)             // 4608

#define NBLK  120                 // <= SM count: all blocks co-resident (barrier-safe)
#define NTHR  1024
#define NALL  (NBLK * NTHR)

#define EPT   (23 * 768)
#define EPI   (2 * EPT)
#define NEDGE (BB * EPI)          // 282624

#define SCALEF 16777216.0f        // 2^24 fixed point: order-invariant error sums

// Scratch (static __device__ arrays; allocation-free kernel_launch).
__device__ int    g_pp[NTOT];     // pred UF parents (tile-root entries only)
__device__ int    g_pt[NTOT];     // target UF parents (tile-root entries only)
__device__ int2   g_mm[NTOT];     // {min,max} target root per pred root
__device__ unsigned long long g_S[NTOT];  // per pred tile-root: fixed-point err sum
__device__ int    g_edge[2][NTILES * 128];// tile edge roots [mask][(tile*4+e)*32+pos]
__device__ int2   g_wl[NTOT];     // dedup'd overlap pairs (predRootGi, targRootGi)
__device__ int    g_rl[NTOT / 2]; // pred tile-root list
__device__ int    g_rlt[NTOT / 2];// target tile-root list
__device__ int    g_nwl, g_nrl, g_nrlt;   // counters (zeroed in phase 0)
__device__ int    g_flags[NBLK];
__device__ double g_psum[NBLK];
__device__ unsigned long long g_esum[NBLK];
__device__ unsigned g_bar_count, g_bar_epoch;   // zero-init; epoch monotonic

// Exact reference arithmetic for (x + 1.0) * 0.5 without FMA contraction.
__device__ __forceinline__ float resc01(float x) {
    return __fmul_rn(__fadd_rn(x, 1.0f), 0.5f);
}

// ---------------------------------------------------------------------------
// Software grid barrier (valid: all NBLK blocks co-resident).
// ---------------------------------------------------------------------------
__device__ __forceinline__ void grid_sync() {
    __syncthreads();
    if (threadIdx.x == 0) {
        __threadfence();
        unsigned e = atomicAdd(&g_bar_epoch, 0u);      // read epoch BEFORE arriving
        unsigned v = atomicAdd(&g_bar_count, 1u);
        if (v == NBLK - 1) {
            g_bar_count = 0;
            __threadfence();
            atomicAdd(&g_bar_epoch, 1u);               // release
        } else {
            while (atomicAdd(&g_bar_epoch, 0u) == e) __nanosleep(64);
        }
        __threadfence();
    }
    __syncthreads();
}

// ---------------------------------------------------------------------------
// Union-find (min-index rooting; parent <= child invariant)
// ---------------------------------------------------------------------------
__device__ __forceinline__ int uf_find(const int* L, int x) {
    int p = L[x];
    while (p != x) { x = p; p = L[x]; }
    return x;
}

__device__ __forceinline__ int uf_findc(int* L, int x) {   // find + compress
    int r = x, p = L[r];
    while (p != r) { r = p; p = L[r]; }
    while (L[x] != r) { int nx = L[x]; L[x] = r; x = nx; }
    return r;
}

__device__ __forceinline__ void uf_union(int* L, int a, int b) {
    int ra = uf_find(L, a);
    int rb = uf_find(L, b);
    while (ra != rb) {
        int hi = ra > rb ? ra : rb;
        int lo = ra > rb ? rb : ra;
        int old = atomicMin(&L[hi], lo);
        if (old == hi) break;
        ra = lo;
        rb = old;
    }
}

// Shared-memory union-find.
__device__ __forceinline__ int s_find(const int* L, int x) {
    int p = L[x];
    while (p != x) { x = p; p = L[x]; }
    return x;
}

__device__ __forceinline__ void s_union(int* L, int a, int b) {
    int ra = s_find(L, a);
    int rb = s_find(L, b);
    while (ra != rb) {
        int hi = ra > rb ? ra : rb;
        int lo = ra > rb ? rb : ra;
        int old = atomicMin(&L[hi], lo);
        if (old == hi) break;
        ra = lo;
        rb = old;
    }
}

// Warp-aggregated slot reservation in a shared counter. All 32 lanes call.
__device__ __forceinline__ int warp_reserve(int* scnt, bool pred) {
    unsigned b = __ballot_sync(0xffffffffu, pred);
    int cnt = __popc(b);
    if (cnt == 0) return -1;
    int lane = threadIdx.x & 31;
    int leader = __ffs(b) - 1;
    int base = 0;
    if (lane == leader) base = atomicAdd(scnt, cnt);
    base = __shfl_sync(0xffffffffu, base, leader);
    return pred ? base + __popc(b & ((1u << lane) - 1)) : -1;
}

// ---------------------------------------------------------------------------
// The mega kernel
// ---------------------------------------------------------------------------
__global__ void __launch_bounds__(NTHR, 1)
k_all(const float* __restrict__ pred, const float* __restrict__ target,
      float* __restrict__ out) {
    __shared__ int lp[TS * TS];
    __shared__ int lt[TS * TS];
    __shared__ unsigned long long sS[TS * TS];   // also reused as reduce buffer
    __shared__ int scnt[3], sgbase[3];

    int tid = threadIdx.x, bid = blockIdx.x;
    int lane = tid & 31;
    int ly = tid >> 5;

    // ---- Phase 0: rescale flag over pred; zero counters -------------------
    {
        bool neg = false;
        const float4* p4 = (const float4*)pred;
        for (int i = bid * NTHR + tid; i < N4; i += NALL) {
            float4 v = p4[i];
            neg |= (v.x < 0.f) | (v.y < 0.f) | (v.z < 0.f) | (v.w < 0.f);
        }
        int bn = __syncthreads_or((int)neg);
        if (tid == 0) g_flags[bid] = bn;
        if (bid == 0 && tid == 0) { g_nwl = 0; g_nrl = 0; g_nrlt = 0; }
    }
    grid_sync();
    bool resc;
    {
        int r = (tid < NBLK) ? g_flags[tid] : 0;
        resc = __syncthreads_or(r) != 0;
    }

    // ---- Phase 1: per-tile CCL + per-component sums + worklists ------------
    double bacc = 0.0;
    for (int tile = bid; tile < NTILES; tile += NBLK) {
        int b = tile / TPI, tr = tile % TPI;
        int tyi = tr / TILES_X, txi = tr % TILES_X;
        int gbase = b * HWSZ + tyi * TS * WW + txi * TS;
        int gi = gbase + ly * WW + lane;

        float p = pred[gi], t = target[gi];
        float pp  = resc ? resc01(p) : p;
        float t01 = resc01(t);
        bool mp = pp  > 0.5f;
        bool mt = t01 > 0.5f;
        float pl = fabsf(pp - t01);
        bacc += (double)pl;

        lp[tid] = mp ? tid : -1;
        lt[tid] = mt ? tid : -1;
        sS[tid] = 0ull;
        if (tid < 3) scnt[tid] = 0;
        __syncthreads();

        if (mp) {
            if (lane > 0 && lp[tid - 1]  >= 0) s_union(lp, tid, tid - 1);
            if (ly   > 0 && lp[tid - TS] >= 0) s_union(lp, tid, tid - TS);
        }
        if (mt) {
            if (lane > 0 && lt[tid - 1]  >= 0) s_union(lt, tid, tid - 1);
            if (ly   > 0 && lt[tid - TS] >= 0) s_union(lt, tid, tid - TS);
        }
        __syncthreads();

        int rp = mp ? s_find(lp, tid) : -1;
        int rt = mt ? s_find(lt, tid) : -1;
        if (mp && !mt) atomicAdd(&sS[rp], __float2ull_rn(pl * SCALEF));
        __syncthreads();

        int rpg = rp >= 0 ? gbase + (rp >> 5) * WW + (rp & 31) : -1;
        int rtg = rt >= 0 ? gbase + (rt >> 5) * WW + (rt & 31) : -1;
        bool rootp = (rp == tid);
        bool roott = (rt == tid);
        if (rootp) {
            g_pp[gi] = gi;
            g_mm[gi] = make_int2(INT_MAX, -1);
            g_S[gi]  = sS[tid];
        }
        if (roott) g_pt[gi] = gi;

        int slot_rl  = warp_reserve(&scnt[0], rootp);
        int slot_rlt = warp_reserve(&scnt[1], roott);
        bool pair = mp && mt;
        int key = pair ? ((rp << 10) | rt) : -1;
        unsigned grp = __match_any_sync(0xffffffffu, key);
        bool plead = pair && ((__ffs(grp) - 1) == lane);
        int slot_wl = warp_reserve(&scnt[2], plead);
        __syncthreads();

        if (tid == 0) {
            sgbase[0] = scnt[0] ? atomicAdd(&g_nrl,  scnt[0]) : 0;
            sgbase[1] = scnt[1] ? atomicAdd(&g_nrlt, scnt[1]) : 0;
            sgbase[2] = scnt[2] ? atomicAdd(&g_nwl,  scnt[2]) : 0;
        }
        __syncthreads();

        if (slot_rl  >= 0) g_rl [sgbase[0] + slot_rl]  = gi;
        if (slot_rlt >= 0) g_rlt[sgbase[1] + slot_rlt] = gi;
        if (slot_wl  >= 0) g_wl [sgbase[2] + slot_wl]  = make_int2(rpg, rtg);

        int e4 = tile * 4;
        if (ly == 0)       { g_edge[0][(e4+0)*32+lane] = rpg; g_edge[1][(e4+0)*32+lane] = rtg; }
        if (ly == TS - 1)  { g_edge[0][(e4+1)*32+lane] = rpg; g_edge[1][(e4+1)*32+lane] = rtg; }
        if (lane == 0)     { g_edge[0][(e4+2)*32+ly]   = rpg; g_edge[1][(e4+2)*32+ly]   = rtg; }
        if (lane == TS - 1){ g_edge[0][(e4+3)*32+ly]   = rpg; g_edge[1][(e4+3)*32+ly]   = rtg; }
        __syncthreads();   // protect smem before next tile
    }

    // Deterministic base-sum block reduction (fixed per-thread tile order).
    {
        double* shd = (double*)sS;
        shd[tid] = bacc;
        __syncthreads();
        for (int off = NTHR / 2; off > 0; off >>= 1) {
            if (tid < off) shd[tid] += shd[tid + off];
            __syncthreads();
        }
        if (tid == 0) g_psum[bid] = shd[0];
    }
    grid_sync();

    // ---- Phase 2: boundary merge over exported edge roots ------------------
    for (int e0 = bid * NTHR + tid; e0 < NEDGE; e0 += NALL) {
        int b = e0 / EPI, r = e0 % EPI;
        int aIdx, cIdx;
        if (r < EPT) {                               // vertical boundary
            int bi = r / HH, y = r % HH;
            int tl = (b * TILES_Y + (y >> 5)) * TILES_X + bi;
            aIdx = (tl * 4 + 3) * 32 + (y & 31);
            cIdx = ((tl + 1) * 4 + 2) * 32 + (y & 31);
        } else {                                     // horizontal boundary
            r -= EPT;
            int bi = r / WW, x = r % WW;
            int tt = (b * TILES_Y + bi) * TILES_X + (x >> 5);
            aIdx = (tt * 4 + 1) * 32 + (x & 31);
            cIdx = ((tt + TILES_X) * 4 + 0) * 32 + (x & 31);
        }
        int a = g_edge[0][aIdx], c = g_edge[0][cIdx];
        if (a >= 0 && c >= 0) uf_union(g_pp, a, c);
        a = g_edge[1][aIdx]; c = g_edge[1][cIdx];
        if (a >= 0 && c >= 0) uf_union(g_pt, a, c);
    }
    grid_sync();

    int nrl = g_nrl, nrlt = g_nrlt, nwl = g_nwl;

    // ---- Phase 3: compress every tile-root entry to its final root ---------
    for (int i = bid * NTHR + tid; i < nrl;  i += NALL) uf_findc(g_pp, g_rl[i]);
    for (int i = bid * NTHR + tid; i < nrlt; i += NALL) uf_findc(g_pt, g_rlt[i]);
    grid_sync();

    // ---- Phase 4: min/max aggregation over dedup'd overlap pairs -----------
    for (int i = bid * NTHR + tid; i < nwl; i += NALL) {
        int2 pr = g_wl[i];
        int rpf = g_pp[pr.x];     // 1 hop: entries flattened in phase 3
        int rtf = g_pt[pr.y];
        atomicMin(&g_mm[rpf].x, rtf);
        atomicMax(&g_mm[rpf].y, rtf);
    }
    grid_sync();

    // ---- Phase 5: merged-component error sum (order-invariant u64) ---------
    {
        unsigned long long es = 0ull;
        for (int i = bid * NTHR + tid; i < nrl; i += NALL) {
            int r = g_rl[i];
            int R = g_pp[r];
            int2 mm = g_mm[R];
            if (mm.y > mm.x) es += g_S[r];
        }
        sS[tid] = es;
        __syncthreads();
        for (int off = NTHR / 2; off > 0; off >>= 1) {
            if (tid < off) sS[tid] += sS[tid + off];
            __syncthreads();
        }
        if (tid == 0) g_esum[bid] = sS[0];
    }
    grid_sync();

    // ---- Final: block 0 deterministic reduce + output ----------------------
    if (bid == 0) {
        double* shd = (double*)sS;
        shd[tid] = (tid < NBLK) ? g_psum[tid] : 0.0;
        __syncthreads();
        for (int off = NTHR / 2; off > 0; off >>= 1) {
            if (tid < off) shd[tid] += shd[tid + off];
            __syncthreads();
        }
        double base = shd[0];
        __syncthreads();
        sS[tid] = (tid < NBLK) ? g_esum[tid] : 0ull;
        __syncthreads();
        for (int off = NTHR / 2; off > 0; off >>= 1) {
            if (tid < off) sS[tid] += sS[tid + off];
            __syncthreads();
        }
        if (tid == 0) {
            double total = base + 10.0 * ((double)sS[0] / (double)SCALEF);
            out[0] = (float)(total / (double)NTOT);
        }
    }
}

// ---------------------------------------------------------------------------
extern "C" void kernel_launch(void* const* d_in, const int* in_sizes, int n_in,
                              void* d_out, int out_size) {
    const float* pred   = (const float*)d_in[0];
    const float* target = (const float*)d_in[1];
    float* out = (float*)d_out;
    k_all<<<NBLK, NTHR>>>(pred, target, out);
}

// round 9
// speedup vs baseline: 2.2460x; 2.2460x over previous
#include <cuda_runtime.h>
#include <climits>

// Fixed problem shape: B=8, C=1, H=W=768.
#define BB    8
#define HH    768
#define WW    768
#define HWSZ  (HH * WW)          // 589824
#define NTOT  (BB * HWSZ)        // 4718592
#define N4    (NTOT / 4)         // 1179648

#define TS        32
#define TILES_X   24
#define TILES_Y   24

#define EPT   (23 * 768)         // per-image boundary edges, one orientation
#define EPI   (2 * EPT)          // 35328
#define NEDGE (BB * EPI)         // 282624 (one thread = one edge, both masks)

#define BG16  0xFFFFu
#define LOSS_BLOCKS (N4 / 256)   // 4608, exact cover

// Scratch (static __device__ arrays; allocation-free kernel_launch).
__device__ unsigned g_loc[NTOT];    // packed tile-local roots: pred | (targ<<16)
__device__ int      g_parp[NTOT];   // pred UF parents (tile-root entries only)
__device__ int      g_part[NTOT];   // target UF parents (tile-root entries only)
__device__ int      g_lab[NTOT];    // final pred root per pixel (-1 = bg)
__device__ int      g_smin[NTOT];   // min target root per pred root (root entries)
__device__ int      g_smax[NTOT];   // max target root per pred root (root entries)
__device__ int      g_flag;         // rescale flag (published fresh each run)
__device__ int      g_neg, g_ctrf;  // k_flag state (zero-init, self-reset)
__device__ int      g_ctr;          // k_loss last-block counter (self-reset)
__device__ double   g_psum[LOSS_BLOCKS];

// Exact reference arithmetic for (x + 1.0) * 0.5 without FMA contraction.
__device__ __forceinline__ float resc01(float x) {
    return __fmul_rn(__fadd_rn(x, 1.0f), 0.5f);
}

// ---------------------------------------------------------------------------
// Union-find (min-index rooting; parent <= child invariant)
// ---------------------------------------------------------------------------
__device__ __forceinline__ int uf_find(const int* L, int x) {
    int p = L[x];
    while (p != x) { x = p; p = L[x]; }
    return x;
}

__device__ __forceinline__ int uf_findc(int* L, int x) {   // find + compress
    int r = x, p = L[r];
    while (p != r) { r = p; p = L[r]; }
    while (L[x] != r) { int nx = L[x]; L[x] = r; x = nx; }
    return r;
}

__device__ __forceinline__ void uf_union(int* L, int a, int b) {
    int ra = uf_find(L, a);
    int rb = uf_find(L, b);
    while (ra != rb) {
        int hi = ra > rb ? ra : rb;
        int lo = ra > rb ? rb : ra;
        int old = atomicMin(&L[hi], lo);
        if (old == hi) break;
        ra = lo;
        rb = old;
    }
}

// Shared-memory union-find.
__device__ __forceinline__ int s_find(const int* L, int x) {
    int p = L[x];
    while (p != x) { x = p; p = L[x]; }
    return x;
}

__device__ __forceinline__ void s_union(int* L, int a, int b) {
    int ra = s_find(L, a);
    int rb = s_find(L, b);
    while (ra != rb) {
        int hi = ra > rb ? ra : rb;
        int lo = ra > rb ? rb : ra;
        int old = atomicMin(&L[hi], lo);
        if (old == hi) break;
        ra = lo;
        rb = old;
    }
}

// Reconstruct global index of a tile-local root from tile base index.
__device__ __forceinline__ int rec_root(int base, unsigned loc) {
    return base + (int)(loc >> 5) * WW + (int)(loc & 31u);
}

// ---------------------------------------------------------------------------
// Kernels
// ---------------------------------------------------------------------------
// Publish the rescale flag fresh each run (last-block pattern; self-resetting).
__global__ void k_flag(const float4* __restrict__ pred) {
    int i = blockIdx.x * blockDim.x + threadIdx.x;
    float4 v = pred[i];
    bool neg = (v.x < 0.f) | (v.y < 0.f) | (v.z < 0.f) | (v.w < 0.f);
    bool bneg = __syncthreads_or(neg);
    __shared__ bool last;
    if (threadIdx.x == 0) {
        if (bneg) atomicOr(&g_neg, 1);
        __threadfence();
        last = (atomicAdd(&g_ctrf, 1) == (int)gridDim.x - 1);
    }
    __syncthreads();
    if (last && threadIdx.x == 0) { g_flag = g_neg; g_neg = 0; g_ctrf = 0; }
}

// Per 32x32 tile: masks, in-tile CCL in smem; store packed 16-bit local roots.
// UF parents + smin/smax initialized ONLY at tile-root pixels.
__global__ void k_tile(const float* __restrict__ pred,
                       const float* __restrict__ target) {
    __shared__ int lp[TS * TS];
    __shared__ int lt[TS * TS];
    int lx = threadIdx.x, ly = threadIdx.y;
    int l  = ly * TS + lx;
    int gx = blockIdx.x * TS + lx;
    int gy = blockIdx.y * TS + ly;
    int b  = blockIdx.z;
    int gi = b * HWSZ + gy * WW + gx;

    bool  resc = (g_flag != 0);
    float p = pred[gi];
    float t = target[gi];
    float pp  = resc ? resc01(p) : p;
    float t01 = resc01(t);
    bool mp = pp  > 0.5f;
    bool mt = t01 > 0.5f;

    lp[l] = mp ? l : -1;
    lt[l] = mt ? l : -1;
    __syncthreads();

    if (mp) {
        if (lx > 0 && lp[l - 1]  >= 0) s_union(lp, l, l - 1);
        if (ly > 0 && lp[l - TS] >= 0) s_union(lp, l, l - TS);
    }
    if (mt) {
        if (lx > 0 && lt[l - 1]  >= 0) s_union(lt, l, l - 1);
        if (ly > 0 && lt[l - TS] >= 0) s_union(lt, l, l - TS);
    }
    __syncthreads();

    unsigned rp16 = BG16, rt16 = BG16;
    if (mp) {
        int r = s_find(lp, l);
        rp16 = (unsigned)r;
        if (r == l) {                 // pred tile-root pixel
            g_parp[gi] = gi;
            g_smin[gi] = INT_MAX;
            g_smax[gi] = -1;
        }
    }
    if (mt) {
        int r = s_find(lt, l);
        rt16 = (unsigned)r;
        if (r == l) g_part[gi] = gi;  // target tile-root pixel
    }
    g_loc[gi] = rp16 | (rt16 << 16);
}

// Merge across tile boundaries; one thread = one edge, handles both masks.
__global__ void k_bmerge() {
    int tid = blockIdx.x * blockDim.x + threadIdx.x;
    if (tid >= NEDGE) return;
    int b = tid / EPI;
    int e = tid % EPI;
    int y, x, ny, nx;
    if (e < EPT) {                       // vertical boundary: (y,x)-(y,x-1)
        int bi = e / HH; y = e % HH;
        x = TS * (bi + 1); ny = y; nx = x - 1;
    } else {                             // horizontal boundary: (y,x)-(y-1,x)
        e -= EPT;
        int bi = e / WW; x = e % WW;
        y = TS * (bi + 1); ny = y - 1; nx = x;
    }
    int idx = b * HWSZ + y * WW + x;
    int n   = b * HWSZ + ny * WW + nx;
    unsigned a = g_loc[idx], c = g_loc[n];
    int abase = b * HWSZ + (y  & ~31) * WW + (x  & ~31);
    int cbase = b * HWSZ + (ny & ~31) * WW + (nx & ~31);

    if ((a & BG16) != BG16 && (c & BG16) != BG16)
        uf_union(g_parp, rec_root(abase, a & BG16), rec_root(cbase, c & BG16));
    if ((a >> 16) != BG16 && (c >> 16) != BG16)
        uf_union(g_part, rec_root(abase, a >> 16), rec_root(cbase, c >> 16));
}

// Per pixel: resolve final roots (compressing chase from tile root), write the
// final pred root for the loss pass, and feed smin/smax atomics on overlaps.
__global__ void k_flat_agg() {
    int i = blockIdx.x * blockDim.x + threadIdx.x;   // exact cover of NTOT
    unsigned v = g_loc[i];
    unsigned pl = v & BG16, tl = v >> 16;
    int rem  = i % HWSZ;
    int base = (i - rem) + ((rem / WW) & ~31) * WW + ((rem % WW) & ~31);

    int rp = -1, rt = -1;
    if (pl != BG16) rp = uf_findc(g_parp, rec_root(base, pl));
    if (tl != BG16) rt = uf_findc(g_part, rec_root(base, tl));
    g_lab[i] = rp;
    if (rp >= 0 && rt >= 0) {
        atomicMin(&g_smin[rp], rt);
        atomicMax(&g_smax[rp], rt);
    }
}

// Weighted loss + fused deterministic final reduction (last-block pattern).
__global__ void k_loss(const float4* __restrict__ pred,
                       const float4* __restrict__ target,
                       float* __restrict__ out) {
    __shared__ double sh[256];
    bool resc = (g_flag != 0);
    int v = blockIdx.x * blockDim.x + threadIdx.x;   // exact cover of N4
    float4 p = pred[v];
    float4 t = target[v];
    int4   a = ((const int4*)g_lab)[v];
    float pv[4] = {p.x, p.y, p.z, p.w};
    float tv[4] = {t.x, t.y, t.z, t.w};
    int   av[4] = {a.x, a.y, a.z, a.w};

    double s = 0.0;
    #pragma unroll
    for (int j = 0; j < 4; j++) {
        float pp  = resc ? resc01(pv[j]) : pv[j];
        float t01 = resc01(tv[j]);
        float pl  = fabsf(pp - t01);
        float w   = 1.0f;
        if (av[j] >= 0 && !(t01 > 0.5f)) {     // pred fg, target bg
            if (g_smax[av[j]] > g_smin[av[j]]) w = 11.0f;   // merged component
        }
        s += (double)(pl * w);
    }

    sh[threadIdx.x] = s;
    __syncthreads();
    for (int off = 128; off > 0; off >>= 1) {
        if (threadIdx.x < off) sh[threadIdx.x] += sh[threadIdx.x + off];
        __syncthreads();
    }
    __shared__ bool last;
    if (threadIdx.x == 0) {
        g_psum[blockIdx.x] = sh[0];
        __threadfence();
        last = (atomicAdd(&g_ctr, 1) == (int)gridDim.x - 1);
    }
    __syncthreads();

    if (last) {
        double s2 = 0.0;
        for (int k = 0; k < LOSS_BLOCKS / 256; k++)          // fixed order
            s2 += g_psum[threadIdx.x + 256 * k];
        sh[threadIdx.x] = s2;
        __syncthreads();
        for (int off = 128; off > 0; off >>= 1) {
            if (threadIdx.x < off) sh[threadIdx.x] += sh[threadIdx.x + off];
            __syncthreads();
        }
        if (threadIdx.x == 0) {
            out[0] = (float)(sh[0] / (double)NTOT);
            g_ctr = 0;                                       // reset for replay
        }
    }
}

// ---------------------------------------------------------------------------
extern "C" void kernel_launch(void* const* d_in, const int* in_sizes, int n_in,
                              void* d_out, int out_size) {
    const float* pred   = (const float*)d_in[0];
    const float* target = (const float*)d_in[1];
    float* out = (float*)d_out;

    k_flag<<<N4 / 256, 256>>>((const float4*)pred);
    k_tile<<<dim3(TILES_X, TILES_Y, BB), dim3(TS, TS)>>>(pred, target);
    k_bmerge<<<(NEDGE + 255) / 256, 256>>>();
    k_flat_agg<<<NTOT / 256, 256>>>();
    k_loss<<<LOSS_BLOCKS, 256>>>((const float4*)pred, (const float4*)target, out);
}